// round 6
// baseline (speedup 1.0000x reference)
#include <cuda_runtime.h>
#include <cuda_bf16.h>

#define BATCH   2
#define CH      256
#define FH      96
#define FW      96
#define FHW     (FH * FW)
#define POOLED  7
#define NBINS   (POOLED * POOLED)
#define N_ROIS  512
#define SPATIAL_SCALE 0.0625f
#define TRANS_STD     0.1f

#define CH_HALF 128
#define ROW_BYTES (FW * CH * 4)
#define COL_BYTES (CH * 4)

// NHWC f32 scratch copy of the feature map: 18.9 MB (L2-resident)
__device__ __align__(128) float g_feat_hwc[BATCH * FHW * CH];

// ---- packed f32x2 helpers (Blackwell FFMA2) ----
__device__ __forceinline__ unsigned long long ffma2(unsigned long long a,
                                                    unsigned long long b,
                                                    unsigned long long c) {
    unsigned long long d;
    asm("fma.rn.f32x2 %0, %1, %2, %3;" : "=l"(d) : "l"(a), "l"(b), "l"(c));
    return d;
}
__device__ __forceinline__ unsigned long long bcast2(float v) {
    unsigned long long r;
    asm("mov.b64 %0, {%1, %1};" : "=l"(r) : "f"(v));
    return r;
}

// ---------------------------------------------------------------------------
// Transpose NCHW -> NHWC via 32x32 shared-memory tiles (coalesced both ways).
// ---------------------------------------------------------------------------
__global__ __launch_bounds__(256) void nchw_to_nhwc_kernel(const float* __restrict__ in) {
    __shared__ float tile[32][33];
    const int b   = blockIdx.z;
    const int hw0 = blockIdx.x * 32;
    const int c0  = blockIdx.y * 32;

    const float* src = in + (size_t)b * CH * FHW;
    #pragma unroll
    for (int j = 0; j < 32; j += 8) {
        tile[threadIdx.y + j][threadIdx.x] =
            src[(size_t)(c0 + threadIdx.y + j) * FHW + hw0 + threadIdx.x];
    }
    __syncthreads();
    float* dst = g_feat_hwc + (size_t)b * FHW * CH;
    #pragma unroll
    for (int j = 0; j < 32; j += 8) {
        dst[(size_t)(hw0 + threadIdx.y + j) * CH + c0 + threadIdx.x] =
            tile[threadIdx.x][threadIdx.y + j];
    }
}

// ---------------------------------------------------------------------------
// Deformable PS-RoI pooling, v6: f32 gathers (LDG.128), packed f32x2 FMA,
// conflict-free [bin][cg] staging, coalesced epilogue.
// Grid (4, 512): blockIdx.x = half*2 + binhalf. 256 threads, warp = bin.
// ---------------------------------------------------------------------------

template <int NB>
__device__ __forceinline__ void store_tile(float* __restrict__ o,
                                           const float* __restrict__ s_outf,
                                           int tid)
{
    #pragma unroll 4
    for (int i = tid; i < CH_HALF * NB; i += 256) {
        const int c = i / NB;
        const int j = i - c * NB;
        o[c * NBINS + j] = s_outf[j * 132 + c];
    }
}

__global__ __launch_bounds__(256, 5) void dpsroi_pool_kernel(
    const float* __restrict__ rois,     // [N_ROIS, 5]
    const float* __restrict__ trans,    // [N_ROIS, 2, 7, 7]
    float* __restrict__ out)            // [N_ROIS, CH, 7, 7]
{
    __shared__ float4 s_out4[25 * 33];        // [bin][33 float4] = 13.2 KB

    const int half = blockIdx.x >> 1;
    const int bh   = blockIdx.x & 1;          // 0 -> bins 0..23, 1 -> 24..48
    const int n    = blockIdx.y;
    const int tid  = threadIdx.x;
    const int cg   = tid & 31;                // float4 channel group in half
    const int bsub = tid >> 5;                // warp id
    const int nb   = 24 + bh;
    const int bin0 = bh * 24;

    const float* roi = rois + n * 5;
    const int   bidx = (int)roi[0];
    const float x1 = rintf(roi[1]) * SPATIAL_SCALE - 0.5f;
    const float y1 = rintf(roi[2]) * SPATIAL_SCALE - 0.5f;
    const float x2 = (rintf(roi[3]) + 1.0f) * SPATIAL_SCALE - 0.5f;
    const float y2 = (rintf(roi[4]) + 1.0f) * SPATIAL_SCALE - 0.5f;
    const float rw = fmaxf(x2 - x1, 0.1f);
    const float rh = fmaxf(y2 - y1, 0.1f);
    const float bin_w = rw * (1.0f / POOLED);
    const float bin_h = rh * (1.0f / POOLED);
    const float sub_w = bin_w * 0.5f;
    const float sub_h = bin_h * 0.5f;

    const char* __restrict__ featb =
        (const char*)(g_feat_hwc + (size_t)bidx * FHW * CH + half * CH_HALF) + cg * 16;

    const float* trans_n = trans + (size_t)n * 2 * NBINS;

    #pragma unroll 1
    for (int b0 = 0; b0 < 32; b0 += 8) {
        const int lb = b0 + bsub;
        if (lb < nb) {
            const int bin = bin0 + lb;
            const int ph = bin / POOLED;
            const int pw = bin % POOLED;

            const float tx = __ldg(trans_n + bin) * TRANS_STD;
            const float ty = __ldg(trans_n + NBINS + bin) * TRANS_STD;

            const float wstart = (float)pw * bin_w + x1 + tx * rw;
            const float hstart = (float)ph * bin_h + y1 + ty * rh;

            const float w0 = wstart, w1 = wstart + sub_w;
            const float h0 = hstart, h1 = hstart + sub_h;

            const float vx0 = (w0 >= -0.5f && w0 <= (float)FW - 0.5f) ? 1.0f : 0.0f;
            const float vx1 = (w1 >= -0.5f && w1 <= (float)FW - 0.5f) ? 1.0f : 0.0f;
            const float vy0 = (h0 >= -0.5f && h0 <= (float)FH - 0.5f) ? 1.0f : 0.0f;
            const float vy1 = (h1 >= -0.5f && h1 <= (float)FH - 0.5f) ? 1.0f : 0.0f;

            const float wc0 = fminf(fmaxf(w0, 0.0f), (float)FW - 1.0f);
            const float wc1 = fminf(fmaxf(w1, 0.0f), (float)FW - 1.0f);
            const float hc0 = fminf(fmaxf(h0, 0.0f), (float)FH - 1.0f);
            const float hc1 = fminf(fmaxf(h1, 0.0f), (float)FH - 1.0f);

            const float fx0 = floorf(wc0), fx1 = floorf(wc1);
            const float fy0 = floorf(hc0), fy1 = floorf(hc1);
            const float dx0 = wc0 - fx0, dx1 = wc1 - fx1;
            const float dy0 = hc0 - fy0, dy1 = hc1 - fy1;

            const int colv[4] = {
                (int)fx0 * COL_BYTES, (int)ceilf(wc0) * COL_BYTES,
                (int)fx1 * COL_BYTES, (int)ceilf(wc1) * COL_BYTES };
            const int rowv[4] = {
                (int)fy0 * ROW_BYTES, (int)ceilf(hc0) * ROW_BYTES,
                (int)fy1 * ROW_BYTES, (int)ceilf(hc1) * ROW_BYTES };

            const float count = (vx0 + vx1) * (vy0 + vy1);
            const float inv = (count > 0.0f) ? (1.0f / count) : 0.0f;

            // packed broadcast coefficients (inv folded into ay)
            const unsigned long long axp[4] = {
                bcast2(vx0 * (1.0f - dx0)), bcast2(vx0 * dx0),
                bcast2(vx1 * (1.0f - dx1)), bcast2(vx1 * dx1) };
            const unsigned long long ayp[4] = {
                bcast2(vy0 * (1.0f - dy0) * inv), bcast2(vy0 * dy0 * inv),
                bcast2(vy1 * (1.0f - dy1) * inv), bcast2(vy1 * dy1 * inv) };

            unsigned long long acc0 = 0ULL, acc1 = 0ULL;
            #pragma unroll
            for (int r = 0; r < 4; r++) {
                unsigned long long rs0 = 0ULL, rs1 = 0ULL;
                #pragma unroll
                for (int cc = 0; cc < 4; cc++) {
                    const ulonglong2 v =
                        *(const ulonglong2*)(featb + (rowv[r] + colv[cc]));
                    rs0 = ffma2(axp[cc], v.x, rs0);
                    rs1 = ffma2(axp[cc], v.y, rs1);
                }
                acc0 = ffma2(ayp[r], rs0, acc0);
                acc1 = ffma2(ayp[r], rs1, acc1);
            }

            // conflict-free STS.128: [bin][cg], stride 33 float4
            *(ulonglong2*)&s_out4[lb * 33 + cg] = make_ulonglong2(acc0, acc1);
        }
    }

    __syncthreads();

    float* o = out + ((size_t)n * CH + (size_t)half * CH_HALF) * NBINS + bin0;
    const float* s_outf = (const float*)s_out4;
    if (bh == 0) store_tile<24>(o, s_outf, tid);
    else         store_tile<25>(o, s_outf, tid);
}

extern "C" void kernel_launch(void* const* d_in, const int* in_sizes, int n_in,
                              void* d_out, int out_size)
{
    const float* bottom_data  = (const float*)d_in[0];  // (2,256,96,96)
    const float* bottom_rois  = (const float*)d_in[1];  // (512,5)
    const float* bottom_trans = (const float*)d_in[2];  // (512,2,7,7)
    float* out = (float*)d_out;                         // (512,256,7,7)

    {
        dim3 tb(32, 8);
        dim3 tg(FHW / 32, CH / 32, BATCH);
        nchw_to_nhwc_kernel<<<tg, tb>>>(bottom_data);
    }
    {
        dim3 pg(4, N_ROIS);
        dpsroi_pool_kernel<<<pg, 256>>>(bottom_rois, bottom_trans, out);
    }
}